// round 15
// baseline (speedup 1.0000x reference)
#include <cuda_runtime.h>
#include <cuda_fp16.h>
#include <cstdint>

#define NROWS 4096            // batch rows (2*2048)
#define NFEAT 16384           // 128*128
#define LDW 136               // W smem ld (fp16): 272B rows, ldmatrix conflict-free
#define LDB 72                // B slot smem ld (fp16): 144B rows, ldmatrix conflict-free
#define DSTRIDE ((size_t)128 * 4096)
#define WPL (128 * LDW)       // halves: W full plane (128n x 128k +pad)
#define BSL (64 * LDB)        // halves: one B slot (64k x 64r +pad)
#define NSLOT 4
#define SMEM_BYTES ((WPL + NSLOT * BSL) * 2)   // 71680 B -> 3 CTAs/SM (215KB)

// Scratch (allocation-free rule): ping-pong buffers (used as fp16) + W images.
__device__ float g_bufA[67108864];
__device__ float g_bufB[67108864];
__device__ __half g_wh[2][128 * 16384];   // fp16 W images, row-major [which][blk][n][k]

__device__ __forceinline__ void cp16(uint32_t d, const void* s) {
    asm volatile("cp.async.cg.shared.global [%0], [%1], 16;" :: "r"(d), "l"(s));
}
#define CP_COMMIT() asm volatile("cp.async.commit_group;" ::: "memory")
#define CP_WAIT(n)  asm volatile("cp.async.wait_group %0;" :: "n"(n) : "memory")

// ---------------------------------------------------------------------------
// prep_w: L/R f32 -> fp16 row-major images
// ---------------------------------------------------------------------------
__global__ void prep_w_k(const float* __restrict__ L, const float* __restrict__ R) {
    const int which = blockIdx.y, blk = blockIdx.x, tid = threadIdx.x;
    const float* W = (which ? R : L) + (size_t)blk * 16384;
    __half* img = g_wh[which] + (size_t)blk * 16384;
#pragma unroll
    for (int it = 0; it < 16; ++it) {
        int idx = it * 256 + tid;            // 4096 float4s
        float4 v = *(const float4*)(W + idx * 4);
        __half* d = img + idx * 4;
        ((__half2*)d)[0] = __floats2half2_rn(v.x, v.y);
        ((__half2*)d)[1] = __floats2half2_rn(v.z, v.w);
    }
}

// ---------------------------------------------------------------------------
// T1: xt[c][r] (fp16) = x[r][c] (f32).  64x64 tiles.
// ---------------------------------------------------------------------------
__global__ void __launch_bounds__(256)
t1_k(__half* __restrict__ dst, const float* __restrict__ src) {
    __shared__ float t[64][65];
    const int c0 = blockIdx.x * 64, r0 = blockIdx.y * 64;
    const int tx = threadIdx.x & 15, ty = threadIdx.x >> 4;
#pragma unroll
    for (int k = 0; k < 4; ++k) {
        float4 v = *(const float4*)(src + (size_t)(r0 + ty + 16 * k) * NFEAT + c0 + 4 * tx);
        t[4 * tx + 0][ty + 16 * k] = v.x;
        t[4 * tx + 1][ty + 16 * k] = v.y;
        t[4 * tx + 2][ty + 16 * k] = v.z;
        t[4 * tx + 3][ty + 16 * k] = v.w;
    }
    __syncthreads();
#pragma unroll
    for (int k = 0; k < 4; ++k) {
        const int cl = ty + 16 * k;
        __half2 a = __floats2half2_rn(t[cl][4 * tx + 0], t[cl][4 * tx + 1]);
        __half2 b = __floats2half2_rn(t[cl][4 * tx + 2], t[cl][4 * tx + 3]);
        __half2* p = (__half2*)(dst + (size_t)(c0 + cl) * NROWS + r0 + 4 * tx);
        p[0] = a; p[1] = b;
    }
}

// ---------------------------------------------------------------------------
// T2: out[r][c] (f32) = out2[c][r] (fp16) + bias[c].  64x64 tiles.
// ---------------------------------------------------------------------------
__global__ void __launch_bounds__(256)
t2_k(float* __restrict__ dst, const __half* __restrict__ src,
     const float* __restrict__ bias) {
    __shared__ float t[64][65];
    __shared__ float bias_s[64];
    const int c0 = blockIdx.x * 64, r0 = blockIdx.y * 64;
    const int tx = threadIdx.x & 15, ty = threadIdx.x >> 4;
    if (threadIdx.x < 64) bias_s[threadIdx.x] = bias[c0 + threadIdx.x];
    __syncthreads();
#pragma unroll
    for (int k = 0; k < 4; ++k) {
        const int cl = ty + 16 * k;
        const __half2* p = (const __half2*)(src + (size_t)(c0 + cl) * NROWS + r0 + 4 * tx);
        __half2 a = p[0], b = p[1];
        const float bv = bias_s[cl];
        t[4 * tx + 0][cl] = __low2float(a)  + bv;
        t[4 * tx + 1][cl] = __high2float(a) + bv;
        t[4 * tx + 2][cl] = __low2float(b)  + bv;
        t[4 * tx + 3][cl] = __high2float(b) + bv;
    }
    __syncthreads();
#pragma unroll
    for (int k = 0; k < 4; ++k) {
        const int rl = ty + 16 * k;
        float4 w = make_float4(t[rl][4 * tx + 0], t[rl][4 * tx + 1],
                               t[rl][4 * tx + 2], t[rl][4 * tx + 3]);
        *(float4*)(dst + (size_t)(r0 + rl) * NFEAT + c0 + 4 * tx) = w;
    }
}

// ---------------------------------------------------------------------------
// MMA helpers (f32 accumulate — R14's f16-acc reverted)
// ---------------------------------------------------------------------------
__device__ __forceinline__ void ldsm4(unsigned r[4], const __half* p) {
    unsigned a = (unsigned)__cvta_generic_to_shared(p);
    asm volatile("ldmatrix.sync.aligned.m8n8.x4.shared.b16 {%0,%1,%2,%3}, [%4];"
                 : "=r"(r[0]), "=r"(r[1]), "=r"(r[2]), "=r"(r[3]) : "r"(a));
}
__device__ __forceinline__ void ldsm4t(unsigned r[4], const __half* p) {
    unsigned a = (unsigned)__cvta_generic_to_shared(p);
    asm volatile("ldmatrix.sync.aligned.m8n8.x4.trans.shared.b16 {%0,%1,%2,%3}, [%4];"
                 : "=r"(r[0]), "=r"(r[1]), "=r"(r[2]), "=r"(r[3]) : "r"(a));
}
__device__ __forceinline__ void mma16816(float c[4], const unsigned a[4],
                                         unsigned b0, unsigned b1) {
    asm volatile("mma.sync.aligned.m16n8k16.row.col.f32.f16.f16.f32 "
                 "{%0,%1,%2,%3}, {%4,%5,%6,%7}, {%8,%9}, {%0,%1,%2,%3};"
                 : "+f"(c[0]), "+f"(c[1]), "+f"(c[2]), "+f"(c[3])
                 : "r"(a[0]), "r"(a[1]), "r"(a[2]), "r"(a[3]), "r"(b0), "r"(b1));
}

// ---------------------------------------------------------------------------
// GEMM stage (fp16 I/O): D[n][r] = sum_k W[blk,n,k] * B[k][r]
//  stage 1: B rows = xt[(k*128+blk)],  stage 2: B rows = z[(blk*128+k)]
//  D rows = (n*128+blk).
// R13 ring streaming at R7 occupancy: CTA 128n x 64r per step, 4 r-tiles,
// warp tile 32n x 32r (acc 32 f32 -> ~75 regs), W loaded once, B chunks
// (64k x 64r) through a 4-slot ring (single sync per chunk; issue targets
// slot (c+3)%4, ordered by the chunk-start barrier). 3 CTAs/SM = 24 warps.
// ---------------------------------------------------------------------------
__global__ void __launch_bounds__(256, 3)
gemm_k(__half* __restrict__ dst, const __half* __restrict__ bsrc,
       const __half* __restrict__ wimg, int stage) {
    extern __shared__ __half sh[];
    __half* wsm = sh;                               // [128n][LDW], full K

    const int blk = blockIdx.y;
    const int rbase = blockIdx.x * 256;             // 4 tiles x 64r
    const int tid = threadIdx.x;

    const __half* wsrc = wimg + (size_t)blk * 16384;
    __half* D = dst + (size_t)blk * 4096;

    // issue B chunk c (c = 2*tile + kc) into slot c%NSLOT; one commit group
    auto issueB = [&](int c) {
        const int t = c >> 1, kc = c & 1, s = c & (NSLOT - 1);
        const uint32_t bb = (uint32_t)__cvta_generic_to_shared(sh + WPL + s * BSL);
        const int r0 = rbase + t * 64;
#pragma unroll
        for (int it = 0; it < 2; ++it) {            // 64k x 64r = 512 x 16B
            int idx = it * 256 + tid;
            int k = idx >> 3, q = idx & 7;
            int krow = kc * 64 + k;
            size_t grow = (stage == 1) ? ((size_t)krow * 128 + blk)
                                       : ((size_t)blk * 128 + krow);
            cp16(bb + (uint32_t)(k * LDB + q * 8) * 2,
                 bsrc + grow * 4096 + r0 + q * 8);
        }
        CP_COMMIT();
    };

    // ---- prologue: group0 = W + chunk0, then chunks 1,2 (3 groups in flight)
    {
        const uint32_t wb = (uint32_t)__cvta_generic_to_shared(wsm);
#pragma unroll
        for (int it = 0; it < 8; ++it) {
            int idx = it * 256 + tid;               // 2048 x 16B
            int n = idx >> 4, q = idx & 15;
            cp16(wb + (uint32_t)(n * LDW + q * 8) * 2, wsrc + n * 128 + q * 8);
        }
        // no commit: W joins chunk0's group
    }
    issueB(0);    // commits W + c0
    issueB(1);
    issueB(2);

    const int wid = tid >> 5, lane = tid & 31;
    const int wn = (wid & 3) * 32;      // n offset (4 warps over 128n)
    const int wr = (wid >> 2) * 32;     // r offset (2 warps over 64r)
    const int lrow  = lane & 15;
    const int lcol8 = (lane >> 4) << 3;
    const int erow = lane >> 2;
    const int ecol = (lane & 3) * 2;

    float acc[2][4][4];

    // compute one 64-k chunk (kc) from slot s into acc
    auto compute = [&](int kc, int s) {
        const __half* bsm = sh + WPL + s * BSL;
#pragma unroll
        for (int k0 = 0; k0 < 64; k0 += 16) {
            unsigned Ah[2][4], Bh[2][4];
#pragma unroll
            for (int mt = 0; mt < 2; ++mt)
                ldsm4(Ah[mt], wsm + (wn + mt * 16 + lrow) * LDW + kc * 64 + k0 + lcol8);
#pragma unroll
            for (int h = 0; h < 2; ++h)
                ldsm4t(Bh[h], bsm + (k0 + lrow) * LDB + wr + h * 16 + lcol8);
#pragma unroll
            for (int mt = 0; mt < 2; ++mt)
#pragma unroll
                for (int rt = 0; rt < 4; ++rt) {
                    const int h = rt >> 1, p = (rt & 1) * 2;
                    mma16816(acc[mt][rt], Ah[mt], Bh[h][p], Bh[h][p + 1]);
                }
        }
    };

    // ---- main: 4 tiles x 2 chunks, 4-slot ring, single sync per chunk
#pragma unroll
    for (int t = 0; t < 4; ++t) {
#pragma unroll
        for (int a = 0; a < 2; ++a)
#pragma unroll
            for (int b = 0; b < 4; ++b)
#pragma unroll
                for (int c = 0; c < 4; ++c) acc[a][b][c] = 0.0f;
#pragma unroll
        for (int kc = 0; kc < 2; ++kc) {
            const int c = 2 * t + kc;
            if (c <= 5)      { CP_WAIT(2); }   // chunk c done; 2 still in flight
            else if (c == 6) { CP_WAIT(1); }
            else             { CP_WAIT(0); }
            __syncthreads();                   // also orders slot reuse (c-1 done)
            compute(kc, c & (NSLOT - 1));
            if (c + 3 < 8) issueB(c + 3);      // targets slot (c+3)%4 != c%4
        }
        // epilogue tile t (registers only; overlaps in-flight loads)
        const int r0 = rbase + t * 64;
#pragma unroll
        for (int mt = 0; mt < 2; ++mt)
#pragma unroll
            for (int rt = 0; rt < 4; ++rt) {
                const int n0 = wn + mt * 16 + erow;
                const int rr = r0 + wr + rt * 8 + ecol;
                __half2 h01 = __floats2half2_rn(acc[mt][rt][0], acc[mt][rt][1]);
                __half2 h23 = __floats2half2_rn(acc[mt][rt][2], acc[mt][rt][3]);
                *(__half2*)(D + (size_t)n0 * DSTRIDE + rr)       = h01;
                *(__half2*)(D + (size_t)(n0 + 8) * DSTRIDE + rr) = h23;
            }
    }
}

// ---------------------------------------------------------------------------
extern "C" void kernel_launch(void* const* d_in, const int* in_sizes, int n_in,
                              void* d_out, int out_size) {
    const float* x    = (const float*)d_in[0];
    const float* L    = (const float*)d_in[1];
    const float* R    = (const float*)d_in[2];
    const float* bias = (const float*)d_in[3];
    float* out = (float*)d_out;

    float *pA, *pB;
    cudaGetSymbolAddress((void**)&pA, g_bufA);
    cudaGetSymbolAddress((void**)&pB, g_bufB);
    __half* hA = (__half*)pA;
    __half* hB = (__half*)pB;
    __half* wh;
    cudaGetSymbolAddress((void**)&wh, g_wh);
    cudaFuncSetAttribute(gemm_k, cudaFuncAttributeMaxDynamicSharedMemorySize, SMEM_BYTES);

    // 0) weights -> fp16 row-major images
    prep_w_k<<<dim3(128, 2), 256>>>(L, R);
    // 1) xt[c][r] = fp16(x[r][c])
    t1_k<<<dim3(NFEAT / 64, NROWS / 64), 256>>>(hA, x);
    // 2) z[(n*128+b)][r] = fp16( sum_m L[b,n,m] * xt[(m*128+b)][r] )
    gemm_k<<<dim3(NROWS / 256, 128), 256, SMEM_BYTES>>>(hB, hA, wh, 1);
    // 3) out2[(i*128+j)][r] = fp16( sum_m R[j,i,m] * z[(j*128+m)][r] )
    gemm_k<<<dim3(NROWS / 256, 128), 256, SMEM_BYTES>>>(hA, hB, wh + (size_t)128 * 16384, 2);
    // 4) out[r][c] = out2[c][r] + bias[c]
    t2_k<<<dim3(NFEAT / 64, NROWS / 64), 256>>>(out, hA, bias);
}

// round 16
// speedup vs baseline: 1.5353x; 1.5353x over previous
#include <cuda_runtime.h>
#include <cuda_fp16.h>
#include <cstdint>

#define NROWS 4096            // batch rows (2*2048)
#define NFEAT 16384           // 128*128
#define LDW 136               // W smem ld (fp16): 272B rows, ldmatrix conflict-free
#define LDB 136               // B slot smem ld (fp16): 272B rows, ldmatrix conflict-free
#define DSTRIDE ((size_t)128 * 4096)
#define WPL (128 * LDW)       // halves: W full plane (128n x 128k +pad)
#define BSL (64 * LDB)        // halves: one B slot (64k x 128r +pad)
#define NSLOT 4
#define SMEM_BYTES ((WPL + NSLOT * BSL) * 2)   // 104448 B -> 2 CTAs/SM (209KB)

// Scratch (allocation-free rule): ping-pong buffers (used as fp16) + W images.
__device__ float g_bufA[67108864];
__device__ float g_bufB[67108864];
__device__ __half g_wh[2][128 * 16384];   // fp16 W images, row-major [which][blk][n][k]

__device__ __forceinline__ void cp16(uint32_t d, const void* s) {
    asm volatile("cp.async.cg.shared.global [%0], [%1], 16;" :: "r"(d), "l"(s));
}
#define CP_COMMIT() asm volatile("cp.async.commit_group;" ::: "memory")
#define CP_WAIT(n)  asm volatile("cp.async.wait_group %0;" :: "n"(n) : "memory")

// ---------------------------------------------------------------------------
// prep_w: L/R f32 -> fp16 row-major images
// ---------------------------------------------------------------------------
__global__ void prep_w_k(const float* __restrict__ L, const float* __restrict__ R) {
    const int which = blockIdx.y, blk = blockIdx.x, tid = threadIdx.x;
    const float* W = (which ? R : L) + (size_t)blk * 16384;
    __half* img = g_wh[which] + (size_t)blk * 16384;
#pragma unroll
    for (int it = 0; it < 16; ++it) {
        int idx = it * 256 + tid;            // 4096 float4s
        float4 v = *(const float4*)(W + idx * 4);
        __half* d = img + idx * 4;
        ((__half2*)d)[0] = __floats2half2_rn(v.x, v.y);
        ((__half2*)d)[1] = __floats2half2_rn(v.z, v.w);
    }
}

// ---------------------------------------------------------------------------
// T1: xt[c][r] (fp16) = x[r][c] (f32).  64x64 tiles.
// ---------------------------------------------------------------------------
__global__ void __launch_bounds__(256)
t1_k(__half* __restrict__ dst, const float* __restrict__ src) {
    __shared__ float t[64][65];
    const int c0 = blockIdx.x * 64, r0 = blockIdx.y * 64;
    const int tx = threadIdx.x & 15, ty = threadIdx.x >> 4;
#pragma unroll
    for (int k = 0; k < 4; ++k) {
        float4 v = *(const float4*)(src + (size_t)(r0 + ty + 16 * k) * NFEAT + c0 + 4 * tx);
        t[4 * tx + 0][ty + 16 * k] = v.x;
        t[4 * tx + 1][ty + 16 * k] = v.y;
        t[4 * tx + 2][ty + 16 * k] = v.z;
        t[4 * tx + 3][ty + 16 * k] = v.w;
    }
    __syncthreads();
#pragma unroll
    for (int k = 0; k < 4; ++k) {
        const int cl = ty + 16 * k;
        __half2 a = __floats2half2_rn(t[cl][4 * tx + 0], t[cl][4 * tx + 1]);
        __half2 b = __floats2half2_rn(t[cl][4 * tx + 2], t[cl][4 * tx + 3]);
        __half2* p = (__half2*)(dst + (size_t)(c0 + cl) * NROWS + r0 + 4 * tx);
        p[0] = a; p[1] = b;
    }
}

// ---------------------------------------------------------------------------
// T2: out[r][c] (f32) = out2[c][r] (fp16) + bias[c].  64x64 tiles.
// ---------------------------------------------------------------------------
__global__ void __launch_bounds__(256)
t2_k(float* __restrict__ dst, const __half* __restrict__ src,
     const float* __restrict__ bias) {
    __shared__ float t[64][65];
    __shared__ float bias_s[64];
    const int c0 = blockIdx.x * 64, r0 = blockIdx.y * 64;
    const int tx = threadIdx.x & 15, ty = threadIdx.x >> 4;
    if (threadIdx.x < 64) bias_s[threadIdx.x] = bias[c0 + threadIdx.x];
    __syncthreads();
#pragma unroll
    for (int k = 0; k < 4; ++k) {
        const int cl = ty + 16 * k;
        const __half2* p = (const __half2*)(src + (size_t)(c0 + cl) * NROWS + r0 + 4 * tx);
        __half2 a = p[0], b = p[1];
        const float bv = bias_s[cl];
        t[4 * tx + 0][cl] = __low2float(a)  + bv;
        t[4 * tx + 1][cl] = __high2float(a) + bv;
        t[4 * tx + 2][cl] = __low2float(b)  + bv;
        t[4 * tx + 3][cl] = __high2float(b) + bv;
    }
    __syncthreads();
#pragma unroll
    for (int k = 0; k < 4; ++k) {
        const int rl = ty + 16 * k;
        float4 w = make_float4(t[rl][4 * tx + 0], t[rl][4 * tx + 1],
                               t[rl][4 * tx + 2], t[rl][4 * tx + 3]);
        *(float4*)(dst + (size_t)(r0 + rl) * NFEAT + c0 + 4 * tx) = w;
    }
}

// ---------------------------------------------------------------------------
// MMA helpers (f32 accumulate)
// ---------------------------------------------------------------------------
__device__ __forceinline__ void ldsm4(unsigned r[4], const __half* p) {
    unsigned a = (unsigned)__cvta_generic_to_shared(p);
    asm volatile("ldmatrix.sync.aligned.m8n8.x4.shared.b16 {%0,%1,%2,%3}, [%4];"
                 : "=r"(r[0]), "=r"(r[1]), "=r"(r[2]), "=r"(r[3]) : "r"(a));
}
__device__ __forceinline__ void ldsm4t(unsigned r[4], const __half* p) {
    unsigned a = (unsigned)__cvta_generic_to_shared(p);
    asm volatile("ldmatrix.sync.aligned.m8n8.x4.trans.shared.b16 {%0,%1,%2,%3}, [%4];"
                 : "=r"(r[0]), "=r"(r[1]), "=r"(r[2]), "=r"(r[3]) : "r"(a));
}
__device__ __forceinline__ void mma16816(float c[4], const unsigned a[4],
                                         unsigned b0, unsigned b1) {
    asm volatile("mma.sync.aligned.m16n8k16.row.col.f32.f16.f16.f32 "
                 "{%0,%1,%2,%3}, {%4,%5,%6,%7}, {%8,%9}, {%0,%1,%2,%3};"
                 : "+f"(c[0]), "+f"(c[1]), "+f"(c[2]), "+f"(c[3])
                 : "r"(a[0]), "r"(a[1]), "r"(a[2]), "r"(a[3]), "r"(b0), "r"(b1));
}

// ---------------------------------------------------------------------------
// GEMM stage (fp16 I/O): D[n][r] = sum_k W[blk,n,k] * B[k][r]
//  stage 1: B rows = xt[(k*128+blk)],  stage 2: B rows = z[(blk*128+k)]
//  D rows = (n*128+blk).
// R13 body (tile-quad, CTA 128n x 128r per step, W loaded once, continuous
// B streaming) upgraded to a 4-slot ring with ONE sync per chunk: issueB(c+3)
// targets slot (c-1)%4, whose consumers already passed the chunk-c barrier,
// so the post-compute barrier is removed.
// ---------------------------------------------------------------------------
__global__ void __launch_bounds__(256, 2)
gemm_k(__half* __restrict__ dst, const __half* __restrict__ bsrc,
       const __half* __restrict__ wimg, int stage) {
    extern __shared__ __half sh[];
    __half* wsm = sh;                               // [128n][LDW], full K

    const int blk = blockIdx.y;
    const int rbase = blockIdx.x * 512;
    const int tid = threadIdx.x;

    const __half* wsrc = wimg + (size_t)blk * 16384;
    __half* D = dst + (size_t)blk * 4096;

    // issue B chunk c (c = 2*tile + kc) into slot c%NSLOT; one commit group
    auto issueB = [&](int c) {
        const int t = c >> 1, kc = c & 1, s = c & (NSLOT - 1);
        const uint32_t bb = (uint32_t)__cvta_generic_to_shared(sh + WPL + s * BSL);
        const int r0 = rbase + t * 128;
#pragma unroll
        for (int it = 0; it < 4; ++it) {
            int idx = it * 256 + tid;               // 1024 x 16B
            int k = idx >> 4, q = idx & 15;
            int krow = kc * 64 + k;
            size_t grow = (stage == 1) ? ((size_t)krow * 128 + blk)
                                       : ((size_t)blk * 128 + krow);
            cp16(bb + (uint32_t)(k * LDB + q * 8) * 2,
                 bsrc + grow * 4096 + r0 + q * 8);
        }
        CP_COMMIT();
    };

    // ---- prologue: group0 = W + chunk0, group1 = chunk1, group2 = chunk2
    {
        const uint32_t wb = (uint32_t)__cvta_generic_to_shared(wsm);
#pragma unroll
        for (int it = 0; it < 8; ++it) {
            int idx = it * 256 + tid;               // 2048 x 16B
            int n = idx >> 4, q = idx & 15;
            cp16(wb + (uint32_t)(n * LDW + q * 8) * 2, wsrc + n * 128 + q * 8);
        }
        // no commit: W joins chunk0's group
    }
    issueB(0);    // commits W + c0
    issueB(1);
    issueB(2);

    const int wid = tid >> 5, lane = tid & 31;
    const int wm = (wid & 1) * 64;
    const int wr = (wid >> 1) * 32;
    const int lrow  = lane & 15;
    const int lcol8 = (lane >> 4) << 3;
    const int erow = lane >> 2;
    const int ecol = (lane & 3) * 2;

    float acc[4][4][4];

    // compute one 64-k chunk (kc) from slot s into acc
    auto compute = [&](int kc, int s) {
        const __half* bsm = sh + WPL + s * BSL;
#pragma unroll
        for (int k0 = 0; k0 < 64; k0 += 16) {
            unsigned Ah[4][4], Bh[2][4];
#pragma unroll
            for (int mt = 0; mt < 4; ++mt)
                ldsm4(Ah[mt], wsm + (wm + mt * 16 + lrow) * LDW + kc * 64 + k0 + lcol8);
#pragma unroll
            for (int h = 0; h < 2; ++h)
                ldsm4t(Bh[h], bsm + (k0 + lrow) * LDB + wr + h * 16 + lcol8);
#pragma unroll
            for (int mt = 0; mt < 4; ++mt)
#pragma unroll
                for (int rt = 0; rt < 4; ++rt) {
                    const int h = rt >> 1, p = (rt & 1) * 2;
                    mma16816(acc[mt][rt], Ah[mt], Bh[h][p], Bh[h][p + 1]);
                }
        }
    };

    // ---- main: 4 tiles x 2 chunks, 4-slot ring, single sync per chunk
#pragma unroll
    for (int t = 0; t < 4; ++t) {
#pragma unroll
        for (int a = 0; a < 4; ++a)
#pragma unroll
            for (int b = 0; b < 4; ++b)
#pragma unroll
                for (int c = 0; c < 4; ++c) acc[a][b][c] = 0.0f;
#pragma unroll
        for (int kc = 0; kc < 2; ++kc) {
            const int c = 2 * t + kc;
            if (c <= 5)      { CP_WAIT(2); }   // chunk c done; 2 still in flight
            else if (c == 6) { CP_WAIT(1); }
            else             { CP_WAIT(0); }
            __syncthreads();                   // also fences slot (c-1)%4 reuse
            compute(kc, c & (NSLOT - 1));
            if (c + 3 < 8) issueB(c + 3);      // slot (c+3)%4 == (c-1)%4, safe
        }
        // epilogue tile t (registers only; overlaps in-flight loads)
        const int r0 = rbase + t * 128;
#pragma unroll
        for (int mt = 0; mt < 4; ++mt)
#pragma unroll
            for (int rt = 0; rt < 4; ++rt) {
                const int n0 = wm + mt * 16 + erow;
                const int rr = r0 + wr + rt * 8 + ecol;
                __half2 h01 = __floats2half2_rn(acc[mt][rt][0], acc[mt][rt][1]);
                __half2 h23 = __floats2half2_rn(acc[mt][rt][2], acc[mt][rt][3]);
                *(__half2*)(D + (size_t)n0 * DSTRIDE + rr)       = h01;
                *(__half2*)(D + (size_t)(n0 + 8) * DSTRIDE + rr) = h23;
            }
    }
}

// ---------------------------------------------------------------------------
extern "C" void kernel_launch(void* const* d_in, const int* in_sizes, int n_in,
                              void* d_out, int out_size) {
    const float* x    = (const float*)d_in[0];
    const float* L    = (const float*)d_in[1];
    const float* R    = (const float*)d_in[2];
    const float* bias = (const float*)d_in[3];
    float* out = (float*)d_out;

    float *pA, *pB;
    cudaGetSymbolAddress((void**)&pA, g_bufA);
    cudaGetSymbolAddress((void**)&pB, g_bufB);
    __half* hA = (__half*)pA;
    __half* hB = (__half*)pB;
    __half* wh;
    cudaGetSymbolAddress((void**)&wh, g_wh);
    cudaFuncSetAttribute(gemm_k, cudaFuncAttributeMaxDynamicSharedMemorySize, SMEM_BYTES);

    // 0) weights -> fp16 row-major images
    prep_w_k<<<dim3(128, 2), 256>>>(L, R);
    // 1) xt[c][r] = fp16(x[r][c])
    t1_k<<<dim3(NFEAT / 64, NROWS / 64), 256>>>(hA, x);
    // 2) z[(n*128+b)][r] = fp16( sum_m L[b,n,m] * xt[(m*128+b)][r] )
    gemm_k<<<dim3(NROWS / 512, 128), 256, SMEM_BYTES>>>(hB, hA, wh, 1);
    // 3) out2[(i*128+j)][r] = fp16( sum_m R[j,i,m] * z[(j*128+m)][r] )
    gemm_k<<<dim3(NROWS / 512, 128), 256, SMEM_BYTES>>>(hA, hB, wh + (size_t)128 * 16384, 2);
    // 4) out[r][c] = out2[c][r] + bias[c]
    t2_k<<<dim3(NFEAT / 64, NROWS / 64), 256>>>(out, hA, bias);
}